// round 3
// baseline (speedup 1.0000x reference)
#include <cuda_runtime.h>

#define BINS   64
#define NB     (BINS * BINS)
#define BATCH  2
#define NELEM  (192 * 224 * 192)   /* 8,257,536 per batch */
#define N4     (NELEM / 4)
#define EPSF   1e-10f

#define MM_BLOCKS   518            /* x-dim; total = 2*518 = 1036 = 7/SM */
#define HIST_BLOCKS 444            /* x-dim; total = 2*444 = 888  = 6/SM */

// Scratch (no allocations allowed). Self-restoring across calls:
// g_hist re-zeroed and g_minmax / g_done reset by the fused final phase.
__device__ unsigned int g_hist[BATCH * NB];   // static-zeroed
__device__ unsigned int g_minmax[8] = {       // [c*2]=min-enc, [c*2+1]=max-enc
    0xFFFFFFFFu, 0u, 0xFFFFFFFFu, 0u,         // combo = arr*2 + b (arr0=fixed)
    0xFFFFFFFFu, 0u, 0xFFFFFFFFu, 0u
};
__device__ unsigned int g_done = 0;

__device__ __forceinline__ unsigned int fenc(float f) {
    unsigned int u = __float_as_uint(f);
    return (u & 0x80000000u) ? ~u : (u | 0x80000000u);
}
__device__ __forceinline__ float fdec(unsigned int e) {
    unsigned int u = (e & 0x80000000u) ? (e & 0x7fffffffu) : ~e;
    return __uint_as_float(u);
}

// Pass 1: forward stream, per-batch min/max of fixed AND warped.
__global__ void minmaxK(const float4* __restrict__ fixedp,
                        const float4* __restrict__ warpedp) {
    int b = blockIdx.y;
    const float4* f4 = fixedp  + (size_t)b * N4;
    const float4* w4 = warpedp + (size_t)b * N4;

    float fmn = 3.4e38f, fmx = -3.4e38f, wmn = 3.4e38f, wmx = -3.4e38f;
    for (int i = blockIdx.x * blockDim.x + threadIdx.x; i < N4;
         i += gridDim.x * blockDim.x) {
        float4 f = f4[i];
        float4 w = w4[i];
        fmn = fminf(fmn, fminf(fminf(f.x, f.y), fminf(f.z, f.w)));
        fmx = fmaxf(fmx, fmaxf(fmaxf(f.x, f.y), fmaxf(f.z, f.w)));
        wmn = fminf(wmn, fminf(fminf(w.x, w.y), fminf(w.z, w.w)));
        wmx = fmaxf(wmx, fmaxf(fmaxf(w.x, w.y), fmaxf(w.z, w.w)));
    }
    #pragma unroll
    for (int o = 16; o; o >>= 1) {
        fmn = fminf(fmn, __shfl_down_sync(0xFFFFFFFFu, fmn, o));
        fmx = fmaxf(fmx, __shfl_down_sync(0xFFFFFFFFu, fmx, o));
        wmn = fminf(wmn, __shfl_down_sync(0xFFFFFFFFu, wmn, o));
        wmx = fmaxf(wmx, __shfl_down_sync(0xFFFFFFFFu, wmx, o));
    }
    __shared__ float s0[8], s1[8], s2[8], s3[8];
    int w = threadIdx.x >> 5, l = threadIdx.x & 31;
    if (l == 0) { s0[w] = fmn; s1[w] = fmx; s2[w] = wmn; s3[w] = wmx; }
    __syncthreads();
    if (threadIdx.x == 0) {
        float a = s0[0], bb = s1[0], c = s2[0], d = s3[0];
        #pragma unroll
        for (int k = 1; k < 8; k++) {
            a = fminf(a, s0[k]); bb = fmaxf(bb, s1[k]);
            c = fminf(c, s2[k]); d = fmaxf(d, s3[k]);
        }
        atomicMin(&g_minmax[(0 * 2 + b) * 2 + 0], fenc(a));
        atomicMax(&g_minmax[(0 * 2 + b) * 2 + 1], fenc(bb));
        atomicMin(&g_minmax[(1 * 2 + b) * 2 + 0], fenc(c));
        atomicMax(&g_minmax[(1 * 2 + b) * 2 + 1], fenc(d));
    }
}

// Pass 2 (REVERSE stream, L2-reuse of pass-1 tail) + fused final reduction.
__global__ void histK(const float* __restrict__ fixedp,
                      const float* __restrict__ warpedp,
                      const float* __restrict__ pred,
                      const float* __restrict__ tru,
                      float* __restrict__ out) {
    int b = blockIdx.y;
    __shared__ unsigned int sh[NB];
    __shared__ float red[8];
    __shared__ float hmarg[2];
    __shared__ unsigned int s_last;
    int t = threadIdx.x;
    int w = t >> 5, l = t & 31;

    for (int i = t; i < NB; i += blockDim.x) sh[i] = 0u;
    __syncthreads();

    float fmn = fdec(g_minmax[(0 * 2 + b) * 2 + 0]);
    float fmx = fdec(g_minmax[(0 * 2 + b) * 2 + 1]);
    float wmn = fdec(g_minmax[(1 * 2 + b) * 2 + 0]);
    float wmx = fdec(g_minmax[(1 * 2 + b) * 2 + 1]);
    float fs = (float)(BINS - 1) / (fmx - fmn + EPSF);
    float ws = (float)(BINS - 1) / (wmx - wmn + EPSF);

    const float4* f4 = (const float4*)(fixedp + (size_t)b * NELEM);
    const float4* w4 = (const float4*)(warpedp + (size_t)b * NELEM);

    // Reverse traversal: read minmaxK's still-resident L2 tail first; leave
    // the array heads resident for next replay's forward minmaxK.
    for (int i = blockIdx.x * blockDim.x + t; i < N4;
         i += gridDim.x * blockDim.x) {
        int j = (N4 - 1) - i;
        float4 f = f4[j];
        float4 wv = w4[j];
        int fi, wi;
        fi = min(max((int)((f.x - fmn) * fs), 0), BINS - 1);
        wi = min(max((int)((wv.x - wmn) * ws), 0), BINS - 1);
        atomicAdd(&sh[fi * BINS + wi], 1u);
        fi = min(max((int)((f.y - fmn) * fs), 0), BINS - 1);
        wi = min(max((int)((wv.y - wmn) * ws), 0), BINS - 1);
        atomicAdd(&sh[fi * BINS + wi], 1u);
        fi = min(max((int)((f.z - fmn) * fs), 0), BINS - 1);
        wi = min(max((int)((wv.z - wmn) * ws), 0), BINS - 1);
        atomicAdd(&sh[fi * BINS + wi], 1u);
        fi = min(max((int)((f.w - fmn) * fs), 0), BINS - 1);
        wi = min(max((int)((wv.w - wmn) * ws), 0), BINS - 1);
        atomicAdd(&sh[fi * BINS + wi], 1u);
    }
    __syncthreads();

    // Flush as packed u64 (halves global-atomic count; counts << 2^32 so
    // the low half can never carry into the high half).
    unsigned long long* gh64 = (unsigned long long*)(g_hist + b * NB);
    const unsigned long long* sh64 = (const unsigned long long*)sh;
    for (int i = t; i < NB / 2; i += blockDim.x) {
        unsigned long long v = sh64[i];
        if (v) atomicAdd(&gh64[i], v);
    }
    __threadfence();
    __syncthreads();

    // Last-block-does-final (canonical threadfence-reduction pattern).
    if (t == 0) {
        unsigned int total = gridDim.x * gridDim.y;
        unsigned int old = atomicAdd(&g_done, 1u);
        s_last = (old == total - 1) ? 1u : 0u;
    }
    __syncthreads();
    if (!s_last) return;

    __threadfence();  // acquire-ish: order g_hist reads after counter observation
    float* shf = (float*)sh;
    const float invN = 1.0f / ((float)NELEM + EPSF);
    float nmi_sum = 0.f;

    for (int bb = 0; bb < BATCH; bb++) {
        unsigned int* gh = g_hist + bb * NB;
        if (t < 2) hmarg[t] = 0.f;

        // Stage histogram -> shared floats, zero global behind us, and
        // accumulate joint entropy in the same sweep.
        float hj = 0.f;
        #pragma unroll
        for (int k = 0; k < NB / 256; k++) {
            int i = t + k * 256;
            float c = (float)__ldcg(&gh[i]);
            gh[i] = 0u;              // self-restore for next call
            shf[i] = c;
            float p = c * invN;
            hj -= p * __logf(p + EPSF);
        }
        #pragma unroll
        for (int o = 16; o; o >>= 1) hj += __shfl_down_sync(0xFFFFFFFFu, hj, o);
        if (l == 0) red[w] = hj;
        __syncthreads();  // shf, red, hmarg all ready

        // Marginals: threads 0-63 row sums (rotated start -> no bank
        // conflicts), threads 64-127 column sums (naturally conflict-free).
        float hterm = 0.f;
        if (t < 64) {
            float rs = 0.f;
            #pragma unroll
            for (int j = 0; j < BINS; j++) rs += shf[t * BINS + ((j + t) & 63)];
            float p = rs * invN;
            hterm = -p * __logf(p + EPSF);
        } else if (t < 128) {
            int c = t - 64;
            float cs = 0.f;
            #pragma unroll
            for (int j = 0; j < BINS; j++) cs += shf[j * BINS + c];
            float p = cs * invN;
            hterm = -p * __logf(p + EPSF);
        }
        #pragma unroll
        for (int o = 16; o; o >>= 1)
            hterm += __shfl_down_sync(0xFFFFFFFFu, hterm, o);
        if (l == 0 && w < 4) atomicAdd(&hmarg[w >> 1], hterm);
        __syncthreads();

        float h_j = 0.f;
        #pragma unroll
        for (int k = 0; k < 8; k++) h_j += red[k];
        float h_f = hmarg[0], h_w = hmarg[1];
        nmi_sum += 2.f * (h_f + h_w - h_j) / (h_f + h_w + EPSF);
        __syncthreads();  // protect shf/red/hmarg before next batch reuses
    }

    if (t == 0) {
        #pragma unroll
        for (int k = 0; k < 4; k++) {          // restore sentinels
            g_minmax[k * 2 + 0] = 0xFFFFFFFFu;
            g_minmax[k * 2 + 1] = 0u;
        }
        g_done = 0u;                            // reset counter for next call
        float mse = 0.f;
        #pragma unroll
        for (int i = 0; i < BATCH * 12; i++) {
            float d = pred[i] - tru[i];
            mse += d * d;
        }
        mse /= (float)(BATCH * 12);
        out[0] = mse - nmi_sum / (float)BATCH;
        __threadfence();
    }
}

extern "C" void kernel_launch(void* const* d_in, const int* in_sizes, int n_in,
                              void* d_out, int out_size) {
    const float* pred    = (const float*)d_in[0];
    const float* tru     = (const float*)d_in[1];
    const float* fixedp  = (const float*)d_in[2];
    const float* warpedp = (const float*)d_in[3];

    dim3 g1(MM_BLOCKS, BATCH);
    minmaxK<<<g1, 256>>>((const float4*)fixedp, (const float4*)warpedp);

    dim3 g2(HIST_BLOCKS, BATCH);
    histK<<<g2, 256>>>(fixedp, warpedp, pred, tru, (float*)d_out);
}